// round 5
// baseline (speedup 1.0000x reference)
#include <cuda_runtime.h>
#include <math.h>

#define BB    32
#define LL    512
#define HIDC  512
#define NHH   8
#define EE    64
#define TOPK  62

// ---------------- device scratch (zero-initialized at module load) ----------------
__device__ float g_Q [BB*LL*HIDC];
__device__ float g_K [BB*LL*HIDC];
__device__ float g_V [BB*LL*HIDC];
__device__ float g_qs[BB*LL*HIDC];
__device__ float g_ks[BB*LL*HIDC];
__device__ float g_vs[BB*LL*HIDC];
__device__ float g_ctx[BB*LL*HIDC];
__device__ float g_hb [BB*LL*HIDC];
__device__ float g_G [BB*LL*LL];      // Gram: G[b,l,l'] = sum_c Q[b,l,c]K[b,l',c]
__device__ float g_R [BB*LL];         // diagonal sums of G
__device__ float g_h [LL];            // band filter impulse response (includes 1/L)
__device__ float g_T [LL*LL];         // circulant filter matrix T[t,l]=h[(t-l)&511]
__device__ float g_wk[BB*TOPK];
__device__ int   g_dk[BB*TOPK];

// ---------------- filter impulse response ----------------
// h[m] = (1/512) * ( sum_{f=102}^{255} 2*cos(2*pi*f*m/512) + cos(pi*m) )
__global__ void init_h() {
    int m = threadIdx.x;
    float acc = 0.f;
    for (int f = 102; f < 256; f++) {
        int ph = (f * m) & (LL - 1);
        acc += 2.0f * cospif((float)ph * (1.0f / 256.0f));
    }
    {   // Nyquist f=256, weight 1
        int ph = (256 * m) & (LL - 1);
        acc += cospif((float)ph * (1.0f / 256.0f));
    }
    g_h[m] = acc * (1.0f / 512.0f);
}

__global__ void init_T() {
    int t = blockIdx.x, l = threadIdx.x;
    g_T[t * LL + l] = g_h[(t - l) & (LL - 1)];
}

// ---------------- NT SGEMM: C = A[M,K] * B[N,K]^T + bias (+res) ----------------
// blockIdx.z selects among up to 3 (B,bias,C) tuples sharing the same A.
template<int RES>
__global__ __launch_bounds__(256)
void sgemm_nt(const float* __restrict__ A0, const float* __restrict__ B0,
              const float* __restrict__ b0, float* __restrict__ C0,
              const float* __restrict__ B1, const float* __restrict__ b1, float* __restrict__ C1,
              const float* __restrict__ B2, const float* __restrict__ b2, float* __restrict__ C2,
              const float* __restrict__ Rres, int M, int N, int K)
{
    __shared__ float As[128][17];
    __shared__ float Bs[64][17];
    const float* A = A0;
    const float* Bw; const float* bias; float* C;
    if (blockIdx.z == 0)      { Bw = B0; bias = b0; C = C0; }
    else if (blockIdx.z == 1) { Bw = B1; bias = b1; C = C1; }
    else                      { Bw = B2; bias = b2; C = C2; }
    int tid = threadIdx.x;
    int tx = tid & 15, ty = tid >> 4;
    int bm = blockIdx.x * 128, bn = blockIdx.y * 64;
    float acc[8][4] = {};
    for (int k0 = 0; k0 < K; k0 += 16) {
        #pragma unroll
        for (int q = 0; q < 2; q++) {
            int v = tid + q * 256;
            int r = v >> 2, c4 = (v & 3) * 4;
            float4 av = *(const float4*)&A[(size_t)(bm + r)*K + k0 + c4];
            As[r][c4+0]=av.x; As[r][c4+1]=av.y; As[r][c4+2]=av.z; As[r][c4+3]=av.w;
        }
        {
            int r = tid >> 2, c4 = (tid & 3) * 4;
            float4 bv = *(const float4*)&Bw[(size_t)(bn + r)*K + k0 + c4];
            Bs[r][c4+0]=bv.x; Bs[r][c4+1]=bv.y; Bs[r][c4+2]=bv.z; Bs[r][c4+3]=bv.w;
        }
        __syncthreads();
        #pragma unroll
        for (int kk = 0; kk < 16; kk++) {
            float a[8], b[4];
            #pragma unroll
            for (int i = 0; i < 8; i++) a[i] = As[ty*8+i][kk];
            #pragma unroll
            for (int j = 0; j < 4; j++) b[j] = Bs[tx*4+j][kk];
            #pragma unroll
            for (int i = 0; i < 8; i++)
                #pragma unroll
                for (int j = 0; j < 4; j++)
                    acc[i][j] += a[i] * b[j];
        }
        __syncthreads();
    }
    #pragma unroll
    for (int i = 0; i < 8; i++) {
        int gr = bm + ty*8 + i;
        #pragma unroll
        for (int j = 0; j < 4; j++) {
            int gc = bn + tx*4 + j;
            float v = acc[i][j] + bias[gc];
            if (RES) v += Rres[(size_t)gr*N + gc];
            C[(size_t)gr*N + gc] = v;
        }
    }
}

// ---------------- batched Gram NT GEMM: G[b] = Q[b] * K[b]^T (over channels) --------
__global__ __launch_bounds__(256)
void gram_nt()
{
    __shared__ float As[128][17];
    __shared__ float Bs[64][17];
    int b = blockIdx.z;
    const float* A  = g_Q + (size_t)b*LL*HIDC;
    const float* Bw = g_K + (size_t)b*LL*HIDC;
    float* C = g_G + (size_t)b*LL*LL;
    int tid = threadIdx.x;
    int tx = tid & 15, ty = tid >> 4;
    int bm = blockIdx.x * 128, bn = blockIdx.y * 64;
    float acc[8][4] = {};
    for (int k0 = 0; k0 < HIDC; k0 += 16) {
        #pragma unroll
        for (int q = 0; q < 2; q++) {
            int v = tid + q * 256;
            int r = v >> 2, c4 = (v & 3) * 4;
            float4 av = *(const float4*)&A[(size_t)(bm + r)*HIDC + k0 + c4];
            As[r][c4+0]=av.x; As[r][c4+1]=av.y; As[r][c4+2]=av.z; As[r][c4+3]=av.w;
        }
        {
            int r = tid >> 2, c4 = (tid & 3) * 4;
            float4 bv = *(const float4*)&Bw[(size_t)(bn + r)*HIDC + k0 + c4];
            Bs[r][c4+0]=bv.x; Bs[r][c4+1]=bv.y; Bs[r][c4+2]=bv.z; Bs[r][c4+3]=bv.w;
        }
        __syncthreads();
        #pragma unroll
        for (int kk = 0; kk < 16; kk++) {
            float a[8], bb[4];
            #pragma unroll
            for (int i = 0; i < 8; i++) a[i] = As[ty*8+i][kk];
            #pragma unroll
            for (int j = 0; j < 4; j++) bb[j] = Bs[tx*4+j][kk];
            #pragma unroll
            for (int i = 0; i < 8; i++)
                #pragma unroll
                for (int j = 0; j < 4; j++)
                    acc[i][j] += a[i] * bb[j];
        }
        __syncthreads();
    }
    #pragma unroll
    for (int i = 0; i < 8; i++)
        #pragma unroll
        for (int j = 0; j < 4; j++)
            C[(size_t)(bm + ty*8 + i)*LL + bn + tx*4 + j] = acc[i][j];
}

// ---------------- diagonal sums: R[b,d] = sum_l G[b, l, (l-d)&511] ----------------
__global__ __launch_bounds__(128)
void diag_sum()
{
    int d = blockIdx.x, b = blockIdx.y, tid = threadIdx.x;
    const float* Gb = g_G + (size_t)b*LL*LL;
    float s = 0.f;
    for (int l = tid; l < LL; l += 128)
        s += Gb[(size_t)l*LL + ((l - d) & (LL - 1))];
    #pragma unroll
    for (int o = 16; o; o >>= 1) s += __shfl_xor_sync(0xffffffffu, s, o);
    __shared__ float ws[4];
    if ((tid & 31) == 0) ws[tid >> 5] = s;
    __syncthreads();
    if (tid == 0) g_R[b*LL + d] = ws[0] + ws[1] + ws[2] + ws[3];
}

// ---------------- circulant filter apply: out[b,t,c] = sum_l T[t,l] X[b,l,c] --------
// blockIdx.z = which*BB + b  (which: 0=Q->qs, 1=K->ks, 2=V->vs)
__global__ __launch_bounds__(256)
void circ_apply()
{
    __shared__ float As[64][17], Bsm[16][64];
    int bz = blockIdx.z;
    int b  = bz & (BB - 1);
    int wsel = bz >> 5;
    const float* X; float* Out;
    if (wsel == 0)      { X = g_Q; Out = g_qs; }
    else if (wsel == 1) { X = g_K; Out = g_ks; }
    else                { X = g_V; Out = g_vs; }
    int t0 = blockIdx.y * 64;
    int n0 = blockIdx.x * 64;
    int tid = threadIdx.x;
    int tx = tid & 15, ty = tid >> 4;
    float acc[4][4] = {};
    for (int k0 = 0; k0 < LL; k0 += 16) {
        {
            int r = tid >> 2, c4 = (tid & 3) * 4;
            float4 av = *(const float4*)&g_T[(size_t)(t0 + r)*LL + k0 + c4];
            As[r][c4+0]=av.x; As[r][c4+1]=av.y; As[r][c4+2]=av.z; As[r][c4+3]=av.w;
        }
        {
            int r = tid >> 4, c4 = (tid & 15) * 4;
            float4 bv = *(const float4*)&X[((size_t)b*LL + k0 + r)*HIDC + n0 + c4];
            Bsm[r][c4+0]=bv.x; Bsm[r][c4+1]=bv.y; Bsm[r][c4+2]=bv.z; Bsm[r][c4+3]=bv.w;
        }
        __syncthreads();
        #pragma unroll
        for (int kk = 0; kk < 16; kk++) {
            float a[4], bv[4];
            #pragma unroll
            for (int i = 0; i < 4; i++) a[i] = As[ty*4+i][kk];
            #pragma unroll
            for (int j = 0; j < 4; j++) bv[j] = Bsm[kk][tx*4+j];
            #pragma unroll
            for (int i = 0; i < 4; i++)
                #pragma unroll
                for (int j = 0; j < 4; j++)
                    acc[i][j] += a[i]*bv[j];
        }
        __syncthreads();
    }
    #pragma unroll
    for (int i = 0; i < 4; i++)
        #pragma unroll
        for (int j = 0; j < 4; j++)
            Out[((size_t)b*LL + t0 + ty*4 + i)*HIDC + n0 + tx*4 + j] = acc[i][j];
}

// ---------------- mean-corr via R*h convolution + top-k + softmax (one block/b) -----
__global__ __launch_bounds__(256)
void mc_topk()
{
    int b = blockIdx.x, tid = threadIdx.x;
    __shared__ float Rs[LL], hs[LL];
    __shared__ float mc[LL];
    __shared__ float bv[256]; __shared__ int bi[256];
    __shared__ float wk[TOPK]; __shared__ int dk[TOPK];
    __shared__ float ev[TOPK]; __shared__ float ssum;

    for (int i = tid; i < LL; i += 256) { Rs[i] = g_R[b*LL + i]; hs[i] = g_h[i]; }
    __syncthreads();

    const float sc = 1.0f / 512.0f;   // 1/(H*E) mean over channels
    for (int t = tid; t < LL; t += 256) {
        float acc = 0.f;
        for (int d = 0; d < LL; d++)
            acc += Rs[d] * hs[(t - d) & (LL - 1)];
        mc[t] = acc * sc;
    }
    __syncthreads();

    for (int k = 0; k < TOPK; k++) {
        float v1 = mc[tid], v2 = mc[tid + 256];
        float vv; int ii;
        if (v2 > v1) { vv = v2; ii = tid + 256; } else { vv = v1; ii = tid; }
        bv[tid] = vv; bi[tid] = ii;
        __syncthreads();
        for (int s = 128; s > 0; s >>= 1) {
            if (tid < s) {
                float ov = bv[tid + s]; int oi = bi[tid + s];
                if (ov > bv[tid] || (ov == bv[tid] && oi < bi[tid])) { bv[tid] = ov; bi[tid] = oi; }
            }
            __syncthreads();
        }
        if (tid == 0) { wk[k] = bv[0]; dk[k] = bi[0]; mc[bi[0]] = -INFINITY; }
        __syncthreads();
    }
    if (tid < TOPK) ev[tid] = expf(wk[tid] - wk[0]);
    __syncthreads();
    if (tid == 0) { float s = 0.f; for (int k = 0; k < TOPK; k++) s += ev[k]; ssum = s; }
    __syncthreads();
    if (tid < TOPK) { g_wk[b*TOPK + tid] = ev[tid] / ssum; g_dk[b*TOPK + tid] = dk[tid]; }
}

// ---------------- flash attention (fp32) per (b,h), writes 0.5*ctx_sp ----------------
__global__ __launch_bounds__(256)
void attn_kernel(const float* __restrict__ mask)
{
    extern __shared__ float smdyn[];
    float* Qs = smdyn;
    float* Ks = Qs + 64*65;
    float* Vs = Ks + 64*65;
    float* Ps = Vs + 64*65;
    __shared__ float rm[64], rl[64], rf[64];
    int bh = blockIdx.z, b = bh >> 3, h = bh & 7;
    int l0 = blockIdx.x * 64;
    int tid = threadIdx.x, tx = tid & 15, ty = tid >> 4;

    for (int v = tid; v < 64*16; v += 256) {
        int r = v >> 4, c4 = (v & 15) * 4;
        float4 qv = *(const float4*)&g_qs[((size_t)b*LL + l0 + r)*HIDC + h*EE + c4];
        Qs[r*65+c4+0]=qv.x; Qs[r*65+c4+1]=qv.y; Qs[r*65+c4+2]=qv.z; Qs[r*65+c4+3]=qv.w;
    }
    if (tid < 64) { rm[tid] = -INFINITY; rl[tid] = 0.f; }
    float acc[4][4] = {};
    __syncthreads();

    for (int m0 = 0; m0 < LL; m0 += 64) {
        for (int v = tid; v < 64*16; v += 256) {
            int r = v >> 4, c4 = (v & 15) * 4;
            size_t base = ((size_t)b*LL + m0 + r)*HIDC + h*EE + c4;
            float4 kv = *(const float4*)&g_ks[base];
            float4 vv = *(const float4*)&g_vs[base];
            Ks[r*65+c4+0]=kv.x; Ks[r*65+c4+1]=kv.y; Ks[r*65+c4+2]=kv.z; Ks[r*65+c4+3]=kv.w;
            Vs[r*65+c4+0]=vv.x; Vs[r*65+c4+1]=vv.y; Vs[r*65+c4+2]=vv.z; Vs[r*65+c4+3]=vv.w;
        }
        __syncthreads();

        float s[4][4] = {};
        #pragma unroll 8
        for (int e = 0; e < 64; e++) {
            float qa[4], kb[4];
            #pragma unroll
            for (int i = 0; i < 4; i++) qa[i] = Qs[(ty*4+i)*65 + e];
            #pragma unroll
            for (int j = 0; j < 4; j++) kb[j] = Ks[(tx*4+j)*65 + e];
            #pragma unroll
            for (int i = 0; i < 4; i++)
                #pragma unroll
                for (int j = 0; j < 4; j++)
                    s[i][j] += qa[i]*kb[j];
        }
        #pragma unroll
        for (int i = 0; i < 4; i++)
            #pragma unroll
            for (int j = 0; j < 4; j++)
                s[i][j] = s[i][j]*0.125f +
                    mask[((size_t)b*LL + l0 + ty*4 + i)*LL + m0 + tx*4 + j];

        float tm[4];
        #pragma unroll
        for (int i = 0; i < 4; i++)
            tm[i] = fmaxf(fmaxf(s[i][0], s[i][1]), fmaxf(s[i][2], s[i][3]));
        #pragma unroll
        for (int o = 1; o < 16; o <<= 1)
            #pragma unroll
            for (int i = 0; i < 4; i++)
                tm[i] = fmaxf(tm[i], __shfl_xor_sync(0xffffffffu, tm[i], o));
        if (tx == 0) {
            #pragma unroll
            for (int i = 0; i < 4; i++) {
                int r = ty*4 + i;
                float mo = rm[r];
                float mn = fmaxf(mo, tm[i]);
                rf[r] = expf(mo - mn);
                rm[r] = mn;
            }
        }
        __syncthreads();

        float ts[4] = {0.f, 0.f, 0.f, 0.f};
        #pragma unroll
        for (int i = 0; i < 4; i++) {
            float mrow = rm[ty*4 + i];
            #pragma unroll
            for (int j = 0; j < 4; j++) {
                float p = expf(s[i][j] - mrow);
                ts[i] += p;
                Ps[(ty*4+i)*65 + tx*4 + j] = p;
            }
        }
        #pragma unroll
        for (int o = 1; o < 16; o <<= 1)
            #pragma unroll
            for (int i = 0; i < 4; i++)
                ts[i] += __shfl_xor_sync(0xffffffffu, ts[i], o);
        if (tx == 0) {
            #pragma unroll
            for (int i = 0; i < 4; i++) {
                int r = ty*4 + i;
                rl[r] = rl[r]*rf[r] + ts[i];
            }
        }
        __syncthreads();

        #pragma unroll
        for (int i = 0; i < 4; i++) {
            float f = rf[ty*4 + i];
            #pragma unroll
            for (int j = 0; j < 4; j++) acc[i][j] *= f;
        }
        #pragma unroll 8
        for (int c = 0; c < 64; c++) {
            float pv[4], vv[4];
            #pragma unroll
            for (int i = 0; i < 4; i++) pv[i] = Ps[(ty*4+i)*65 + c];
            #pragma unroll
            for (int j = 0; j < 4; j++) vv[j] = Vs[c*65 + tx*4 + j];
            #pragma unroll
            for (int i = 0; i < 4; i++)
                #pragma unroll
                for (int j = 0; j < 4; j++)
                    acc[i][j] += pv[i]*vv[j];
        }
        __syncthreads();
    }

    #pragma unroll
    for (int i = 0; i < 4; i++) {
        float inv = 1.0f / rl[ty*4 + i];
        #pragma unroll
        for (int j = 0; j < 4; j++)
            g_ctx[((size_t)b*LL + l0 + ty*4 + i)*HIDC + h*EE + tx*4 + j] =
                0.5f * acc[i][j] * inv;
    }
}

// ---------------- time-delay aggregation: ctx += 0.5 * sum_k w_k * V[(l+d_k)%L] ------
// block handles 8 consecutive l (L1 reuse of V rows across the k-loop)
__global__ __launch_bounds__(256)
void delay_agg()
{
    __shared__ float ws[TOPK]; __shared__ int ds[TOPK];
    int l0 = blockIdx.x * 8, b = blockIdx.y, tid = threadIdx.x;
    if (tid < TOPK) { ws[tid] = g_wk[b*TOPK + tid]; ds[tid] = g_dk[b*TOPK + tid]; }
    __syncthreads();
    int c2 = tid;  // float2 index: 256 threads cover 512 floats
    const float2* Vb = (const float2*)(g_V + (size_t)b*LL*HIDC);
    float2 acc[8];
    #pragma unroll
    for (int i = 0; i < 8; i++) acc[i] = make_float2(0.f, 0.f);
    for (int k = 0; k < TOPK; k++) {
        float w = ws[k]; int d = ds[k];
        #pragma unroll
        for (int i = 0; i < 8; i++) {
            int pos = (l0 + i + d) & (LL - 1);
            float2 v = Vb[(size_t)pos*(HIDC/2) + c2];
            acc[i].x += w*v.x; acc[i].y += w*v.y;
        }
    }
    #pragma unroll
    for (int i = 0; i < 8; i++) {
        size_t off = ((size_t)b*LL + l0 + i)*(HIDC/2) + c2;
        float2* C = (float2*)g_ctx;
        float2 cur = C[off];
        cur.x += 0.5f*acc[i].x; cur.y += 0.5f*acc[i].y;
        C[off] = cur;
    }
}

// ---------------- layernorm ----------------
__global__ __launch_bounds__(128)
void ln_kernel(const float* __restrict__ hb, const float* __restrict__ w,
               const float* __restrict__ bp, float* __restrict__ out)
{
    int row = blockIdx.x, tid = threadIdx.x;
    const float* hr = hb + (size_t)row*HIDC;
    float4 xv = *(const float4*)&hr[tid*4];
    float s  = xv.x + xv.y + xv.z + xv.w;
    float ss = xv.x*xv.x + xv.y*xv.y + xv.z*xv.z + xv.w*xv.w;
    #pragma unroll
    for (int o = 16; o; o >>= 1) {
        s  += __shfl_xor_sync(0xffffffffu, s,  o);
        ss += __shfl_xor_sync(0xffffffffu, ss, o);
    }
    __shared__ float s1[4], s2s[4];
    int wp = tid >> 5;
    if ((tid & 31) == 0) { s1[wp] = s; s2s[wp] = ss; }
    __syncthreads();
    float st  = s1[0] + s1[1] + s1[2] + s1[3];
    float sst = s2s[0] + s2s[1] + s2s[2] + s2s[3];
    float mean = st * (1.0f / HIDC);
    float var  = fmaxf(sst * (1.0f / HIDC) - mean*mean, 0.0f);
    float inv  = rsqrtf(var + 1e-12f);
    int c = tid * 4;
    float4 o4;
    o4.x = w[c+0]*((xv.x - mean)*inv) + bp[c+0];
    o4.y = w[c+1]*((xv.y - mean)*inv) + bp[c+1];
    o4.z = w[c+2]*((xv.z - mean)*inv) + bp[c+2];
    o4.w = w[c+3]*((xv.w - mean)*inv) + bp[c+3];
    *(float4*)&out[(size_t)row*HIDC + c] = o4;
}

// ---------------- launch ----------------
extern "C" void kernel_launch(void* const* d_in, const int* in_sizes, int n_in,
                              void* d_out, int out_size)
{
    const float* x    = (const float*)d_in[0];
    const float* mask = (const float*)d_in[1];
    const float* Wq = (const float*)d_in[2];
    const float* bq = (const float*)d_in[3];
    const float* Wk = (const float*)d_in[4];
    const float* bk = (const float*)d_in[5];
    const float* Wv = (const float*)d_in[6];
    const float* bv = (const float*)d_in[7];
    const float* Wd = (const float*)d_in[8];
    const float* bd = (const float*)d_in[9];
    const float* lw = (const float*)d_in[10];
    const float* lb = (const float*)d_in[11];
    float* out = (float*)d_out;

    float *pQ,*pK,*pV,*pctx,*ph;
    cudaGetSymbolAddress((void**)&pQ,  g_Q);
    cudaGetSymbolAddress((void**)&pK,  g_K);
    cudaGetSymbolAddress((void**)&pV,  g_V);
    cudaGetSymbolAddress((void**)&pctx,g_ctx);
    cudaGetSymbolAddress((void**)&ph,  g_hb);

    const int M = BB * LL;   // 16384

    init_h<<<1, LL>>>();
    init_T<<<LL, LL>>>();

    // fused QKV: one launch, z selects weight set
    dim3 gqkv(M/128, HIDC/64, 3);
    sgemm_nt<0><<<gqkv, 256>>>(x, Wq, bq, pQ, Wk, bk, pK, Wv, bv, pV,
                               nullptr, M, HIDC, HIDC);

    // Gram matrices + diagonal sums -> R
    gram_nt<<<dim3(LL/128, LL/64, BB), 256>>>();
    diag_sum<<<dim3(LL, BB), 128>>>();
    mc_topk<<<BB, 256>>>();

    // band filter via circulant GEMM for qs,ks,vs
    circ_apply<<<dim3(HIDC/64, LL/64, 3*BB), 256>>>();

    cudaFuncSetAttribute(attn_kernel, cudaFuncAttributeMaxDynamicSharedMemorySize,
                         4*64*65*sizeof(float));
    attn_kernel<<<dim3(LL/64, 1, BB*NHH), 256, 4*64*65*sizeof(float)>>>(mask);

    delay_agg<<<dim3(LL/8, BB), 256>>>();

    // output projection + residual
    dim3 gg(M/128, HIDC/64, 1);
    sgemm_nt<1><<<gg, 256>>>(pctx, Wd, bd, ph, Wd, bd, ph, Wd, bd, ph,
                             x, M, HIDC, HIDC);

    ln_kernel<<<M, 128>>>(ph, lw, lb, out);
}

// round 10
// speedup vs baseline: 1.3135x; 1.3135x over previous
#include <cuda_runtime.h>
#include <cstdint>
#include <math.h>

#define BB    32
#define LL    512
#define HIDC  512
#define NHH   8
#define EE    64
#define TOPK  62

// ---------------- device scratch (zero-initialized at module load) ----------------
__device__ float g_Q [BB*LL*HIDC];
__device__ float g_K [BB*LL*HIDC];
__device__ float g_V [BB*LL*HIDC];
__device__ float g_qs[BB*LL*HIDC];
__device__ float g_ks[BB*LL*HIDC];
__device__ float g_vs[BB*LL*HIDC];
__device__ float g_ctx[BB*LL*HIDC];
__device__ float g_hb [BB*LL*HIDC];
__device__ float g_G [BB*LL*LL];      // Gram: G[b,l,l'] = sum_c Q[b,l,c]K[b,l',c]
__device__ float g_R [BB*LL];         // diagonal sums of G
__device__ float g_h [LL];            // band filter impulse response (includes 1/L)
__device__ float g_T [LL*LL];         // circulant filter matrix T[t,l]=h[(t-l)&511]
__device__ float g_wk[BB*TOPK];
__device__ int   g_dk[BB*TOPK];

// ---------------- trig/filter tables ----------------
__global__ void init_h() {
    int m = threadIdx.x;
    float acc = 0.f;
    for (int f = 102; f < 256; f++) {
        int ph = (f * m) & (LL - 1);
        acc += 2.0f * cospif((float)ph * (1.0f / 256.0f));
    }
    {   // Nyquist f=256, weight 1
        int ph = (256 * m) & (LL - 1);
        acc += cospif((float)ph * (1.0f / 256.0f));
    }
    g_h[m] = acc * (1.0f / 512.0f);
}

__global__ void init_T() {
    int t = blockIdx.x, l = threadIdx.x;
    g_T[t * LL + l] = g_h[(t - l) & (LL - 1)];
}

// ---------------- tf32 helpers ----------------
__device__ __forceinline__ unsigned int to_tf32(float x) {
    unsigned int u;
    asm("cvt.rna.tf32.f32 %0, %1;" : "=r"(u) : "f"(x));
    return u;
}

__device__ __forceinline__ void mma_tf32(float* d, const uint4& a, const uint2& b) {
    asm volatile(
        "mma.sync.aligned.m16n8k8.row.col.f32.tf32.tf32.f32 "
        "{%0,%1,%2,%3}, {%4,%5,%6,%7}, {%8,%9}, {%0,%1,%2,%3};\n"
        : "+f"(d[0]), "+f"(d[1]), "+f"(d[2]), "+f"(d[3])
        : "r"(a.x), "r"(a.y), "r"(a.z), "r"(a.w), "r"(b.x), "r"(b.y));
}

// ---------------- tf32 tensor-core GEMM body ----------------
// C[128,64] tile: C = A * op(B), A row-major [M,512], all strides 512, K=512.
// BNN=0: C[m,n] = sum_k A[m,k]*B[n,k]  (B row-major [N,512])
// BNN=1: C[m,n] = sum_k A[m,k]*B[k,n]  (B row-major [512,N=512])
// 256 threads = 8 warps (4x2), warp tile 32x32.
// Smem holds fragment-major tiles: one LDS.128 per A-frag, LDS.64 per B-frag.
template<int RES, int BNN, int BIASF>
__device__ __forceinline__ void mma_gemm_body(
    const float* __restrict__ A, const float* __restrict__ B,
    const float* __restrict__ bias, const float* __restrict__ Rres,
    float* __restrict__ C)
{
    __shared__ unsigned int As2[2048];   // [mt(8)][ks(2)][lane(32)][slot(4)]
    __shared__ unsigned int Bs2[1024];   // [nt(8)][ks(2)][lane(32)][slot(2)]
    int tid = threadIdx.x, lane = tid & 31, wid = tid >> 5;
    int wm = wid >> 1, wn = wid & 1;
    int bm = blockIdx.x * 128, bn = blockIdx.y * 64;

    float acc[2][4][4];
    #pragma unroll
    for (int mi = 0; mi < 2; mi++)
        #pragma unroll
        for (int ni = 0; ni < 4; ni++)
            #pragma unroll
            for (int j = 0; j < 4; j++) acc[mi][ni][j] = 0.f;

    for (int k0 = 0; k0 < 512; k0 += 16) {
        // ---- stage A tile 128x16 into fragment layout ----
        #pragma unroll
        for (int q = 0; q < 2; q++) {
            int v = tid + q * 256;
            int r = v >> 2, c0 = (v & 3) * 4;
            float4 av = *(const float4*)&A[(size_t)(bm + r) * 512 + k0 + c0];
            int mt = r >> 4;
            int ks = c0 >> 3;
            int s  = ((r >> 3) & 1) + ((c0 & 4) ? 2 : 0);
            unsigned int* dst = &As2[((((mt*2 + ks)*32) + ((r & 7) << 2)) << 2) + s];
            dst[0]  = to_tf32(av.x);
            dst[4]  = to_tf32(av.y);
            dst[8]  = to_tf32(av.z);
            dst[12] = to_tf32(av.w);
        }
        // ---- stage B tile into fragment layout ----
        if (BNN == 0) {
            int v = tid;
            int n = v >> 2, c0 = (v & 3) * 4;
            float4 bv = *(const float4*)&B[(size_t)(bn + n) * 512 + k0 + c0];
            int nt = n >> 3, ks = c0 >> 3;
            int s  = (c0 & 4) ? 1 : 0;
            unsigned int* dst = &Bs2[((((nt*2 + ks)*32) + ((n & 7) << 2)) << 1) + s];
            dst[0] = to_tf32(bv.x);
            dst[2] = to_tf32(bv.y);
            dst[4] = to_tf32(bv.z);
            dst[6] = to_tf32(bv.w);
        } else {
            int v = tid;
            int kr = v >> 4, c0 = (v & 15) * 4;
            float4 bv = *(const float4*)&B[(size_t)(k0 + kr) * 512 + bn + c0];
            int kk = kr & 7, ks = kr >> 3;
            int s  = (kk >> 2) & 1;
            int l0 = ((c0 & 7) << 2) | (kk & 3);
            int nt = c0 >> 3;
            unsigned int* dst = &Bs2[((((nt*2 + ks)*32) + l0) << 1) + s];
            dst[0]  = to_tf32(bv.x);
            dst[8]  = to_tf32(bv.y);
            dst[16] = to_tf32(bv.z);
            dst[24] = to_tf32(bv.w);
        }
        __syncthreads();
        // ---- consume 2 k-steps of 8 ----
        #pragma unroll
        for (int ks = 0; ks < 2; ks++) {
            uint4 af[2];
            uint2 bf[4];
            #pragma unroll
            for (int mi = 0; mi < 2; mi++)
                af[mi] = *(const uint4*)&As2[((((wm*2 + mi)*2 + ks)*32) + lane) << 2];
            #pragma unroll
            for (int ni = 0; ni < 4; ni++)
                bf[ni] = *(const uint2*)&Bs2[((((wn*4 + ni)*2 + ks)*32) + lane) << 1];
            #pragma unroll
            for (int mi = 0; mi < 2; mi++)
                #pragma unroll
                for (int ni = 0; ni < 4; ni++)
                    mma_tf32(acc[mi][ni], af[mi], bf[ni]);
        }
        __syncthreads();
    }

    // ---- epilogue ----
    int r0 = bm + wm*32 + (lane >> 2);
    int cb = bn + wn*32 + 2*(lane & 3);
    #pragma unroll
    for (int mi = 0; mi < 2; mi++) {
        int ra = r0 + mi*16;
        int rb = ra + 8;
        #pragma unroll
        for (int ni = 0; ni < 4; ni++) {
            int col = cb + ni*8;
            float b0 = 0.f, b1 = 0.f;
            if (BIASF) { b0 = bias[col]; b1 = bias[col+1]; }
            float2 va, vb;
            va.x = acc[mi][ni][0] + b0; va.y = acc[mi][ni][1] + b1;
            vb.x = acc[mi][ni][2] + b0; vb.y = acc[mi][ni][3] + b1;
            if (RES) {
                va.x += Rres[(size_t)ra*512 + col];   va.y += Rres[(size_t)ra*512 + col+1];
                vb.x += Rres[(size_t)rb*512 + col];   vb.y += Rres[(size_t)rb*512 + col+1];
            }
            *(float2*)&C[(size_t)ra*512 + col] = va;
            *(float2*)&C[(size_t)rb*512 + col] = vb;
        }
    }
}

// ---------------- GEMM kernel instantiations ----------------
__global__ __launch_bounds__(256)
void qkv_mma(const float* __restrict__ A,
             const float* __restrict__ B0, const float* __restrict__ b0, float* __restrict__ C0,
             const float* __restrict__ B1, const float* __restrict__ b1, float* __restrict__ C1,
             const float* __restrict__ B2, const float* __restrict__ b2, float* __restrict__ C2)
{
    const float* Bw; const float* bias; float* C;
    if (blockIdx.z == 0)      { Bw = B0; bias = b0; C = C0; }
    else if (blockIdx.z == 1) { Bw = B1; bias = b1; C = C1; }
    else                      { Bw = B2; bias = b2; C = C2; }
    mma_gemm_body<0,0,1>(A, Bw, bias, nullptr, C);
}

__global__ __launch_bounds__(256)
void gram_mma()
{
    int b = blockIdx.z;
    mma_gemm_body<0,0,0>(g_Q + (size_t)b*LL*HIDC, g_K + (size_t)b*LL*HIDC,
                         nullptr, nullptr, g_G + (size_t)b*LL*LL);
}

__global__ __launch_bounds__(256)
void circ_mma()
{
    int bz = blockIdx.z;
    int b  = bz & (BB - 1);
    int wsel = bz >> 5;
    const float* X; float* Out;
    if (wsel == 0)      { X = g_Q; Out = g_qs; }
    else if (wsel == 1) { X = g_K; Out = g_ks; }
    else                { X = g_V; Out = g_vs; }
    mma_gemm_body<0,1,0>(g_T, X + (size_t)b*LL*HIDC, nullptr, nullptr,
                         Out + (size_t)b*LL*HIDC);
}

__global__ __launch_bounds__(256)
void outproj_mma(const float* __restrict__ A, const float* __restrict__ Bw,
                 const float* __restrict__ bias, const float* __restrict__ Rres,
                 float* __restrict__ C)
{
    mma_gemm_body<1,0,1>(A, Bw, bias, Rres, C);
}

// ---------------- diagonal sums: R[b,d] = sum_l G[b, l, (l-d)&511] ----------------
__global__ __launch_bounds__(128)
void diag_sum()
{
    int d = blockIdx.x, b = blockIdx.y, tid = threadIdx.x;
    const float* Gb = g_G + (size_t)b*LL*LL;
    float s = 0.f;
    for (int l = tid; l < LL; l += 128)
        s += Gb[(size_t)l*LL + ((l - d) & (LL - 1))];
    #pragma unroll
    for (int o = 16; o; o >>= 1) s += __shfl_xor_sync(0xffffffffu, s, o);
    __shared__ float ws[4];
    if ((tid & 31) == 0) ws[tid >> 5] = s;
    __syncthreads();
    if (tid == 0) g_R[b*LL + d] = ws[0] + ws[1] + ws[2] + ws[3];
}

// ---------------- mean-corr via R*h convolution + top-k + softmax (one block/b) -----
__global__ __launch_bounds__(256)
void mc_topk()
{
    int b = blockIdx.x, tid = threadIdx.x;
    __shared__ float Rs[LL], hs[LL];
    __shared__ float mc[LL];
    __shared__ float bv[256]; __shared__ int bi[256];
    __shared__ float wk[TOPK]; __shared__ int dk[TOPK];
    __shared__ float ev[TOPK]; __shared__ float ssum;

    for (int i = tid; i < LL; i += 256) { Rs[i] = g_R[b*LL + i]; hs[i] = g_h[i]; }
    __syncthreads();

    const float sc = 1.0f / 512.0f;   // 1/(H*E) mean over channels
    for (int t = tid; t < LL; t += 256) {
        float acc = 0.f;
        for (int d = 0; d < LL; d++)
            acc += Rs[d] * hs[(t - d) & (LL - 1)];
        mc[t] = acc * sc;
    }
    __syncthreads();

    for (int k = 0; k < TOPK; k++) {
        float v1 = mc[tid], v2 = mc[tid + 256];
        float vv; int ii;
        if (v2 > v1) { vv = v2; ii = tid + 256; } else { vv = v1; ii = tid; }
        bv[tid] = vv; bi[tid] = ii;
        __syncthreads();
        for (int s = 128; s > 0; s >>= 1) {
            if (tid < s) {
                float ov = bv[tid + s]; int oi = bi[tid + s];
                if (ov > bv[tid] || (ov == bv[tid] && oi < bi[tid])) { bv[tid] = ov; bi[tid] = oi; }
            }
            __syncthreads();
        }
        if (tid == 0) { wk[k] = bv[0]; dk[k] = bi[0]; mc[bi[0]] = -INFINITY; }
        __syncthreads();
    }
    if (tid < TOPK) ev[tid] = expf(wk[tid] - wk[0]);
    __syncthreads();
    if (tid == 0) { float s = 0.f; for (int k = 0; k < TOPK; k++) s += ev[k]; ssum = s; }
    __syncthreads();
    if (tid < TOPK) { g_wk[b*TOPK + tid] = ev[tid] / ssum; g_dk[b*TOPK + tid] = dk[tid]; }
}

// ---------------- flash attention (fp32) per (b,h), writes 0.5*ctx_sp ----------------
__global__ __launch_bounds__(256)
void attn_kernel(const float* __restrict__ mask)
{
    extern __shared__ float smdyn[];
    float* Qs = smdyn;
    float* Ks = Qs + 64*65;
    float* Vs = Ks + 64*65;
    float* Ps = Vs + 64*65;
    __shared__ float rm[64], rl[64], rf[64];
    int bh = blockIdx.z, b = bh >> 3, h = bh & 7;
    int l0 = blockIdx.x * 64;
    int tid = threadIdx.x, tx = tid & 15, ty = tid >> 4;

    for (int v = tid; v < 64*16; v += 256) {
        int r = v >> 4, c4 = (v & 15) * 4;
        float4 qv = *(const float4*)&g_qs[((size_t)b*LL + l0 + r)*HIDC + h*EE + c4];
        Qs[r*65+c4+0]=qv.x; Qs[r*65+c4+1]=qv.y; Qs[r*65+c4+2]=qv.z; Qs[r*65+c4+3]=qv.w;
    }
    if (tid < 64) { rm[tid] = -INFINITY; rl[tid] = 0.f; }
    float acc[4][4] = {};
    __syncthreads();

    for (int m0 = 0; m0 < LL; m0 += 64) {
        for (int v = tid; v < 64*16; v += 256) {
            int r = v >> 4, c4 = (v & 15) * 4;
            size_t base = ((size_t)b*LL + m0 + r)*HIDC + h*EE + c4;
            float4 kv = *(const float4*)&g_ks[base];
            float4 vv = *(const float4*)&g_vs[base];
            Ks[r*65+c4+0]=kv.x; Ks[r*65+c4+1]=kv.y; Ks[r*65+c4+2]=kv.z; Ks[r*65+c4+3]=kv.w;
            Vs[r*65+c4+0]=vv.x; Vs[r*65+c4+1]=vv.y; Vs[r*65+c4+2]=vv.z; Vs[r*65+c4+3]=vv.w;
        }
        __syncthreads();

        float s[4][4] = {};
        #pragma unroll 8
        for (int e = 0; e < 64; e++) {
            float qa[4], kb[4];
            #pragma unroll
            for (int i = 0; i < 4; i++) qa[i] = Qs[(ty*4+i)*65 + e];
            #pragma unroll
            for (int j = 0; j < 4; j++) kb[j] = Ks[(tx*4+j)*65 + e];
            #pragma unroll
            for (int i = 0; i < 4; i++)
                #pragma unroll
                for (int j = 0; j < 4; j++)
                    s[i][j] += qa[i]*kb[j];
        }
        #pragma unroll
        for (int i = 0; i < 4; i++)
            #pragma unroll
            for (int j = 0; j < 4; j++)
                s[i][j] = s[i][j]*0.125f +
                    mask[((size_t)b*LL + l0 + ty*4 + i)*LL + m0 + tx*4 + j];

        float tm[4];
        #pragma unroll
        for (int i = 0; i < 4; i++)
            tm[i] = fmaxf(fmaxf(s[i][0], s[i][1]), fmaxf(s[i][2], s[i][3]));
        #pragma unroll
        for (int o = 1; o < 16; o <<= 1)
            #pragma unroll
            for (int i = 0; i < 4; i++)
                tm[i] = fmaxf(tm[i], __shfl_xor_sync(0xffffffffu, tm[i], o));
        if (tx == 0) {
            #pragma unroll
            for (int i = 0; i < 4; i++) {
                int r = ty*4 + i;
                float mo = rm[r];
                float mn = fmaxf(mo, tm[i]);
                rf[r] = expf(mo - mn);
                rm[r] = mn;
            }
        }
        __syncthreads();

        float ts[4] = {0.f, 0.f, 0.f, 0.f};
        #pragma unroll
        for (int i = 0; i < 4; i++) {
            float mrow = rm[ty*4 + i];
            #pragma unroll
            for (int j = 0; j < 4; j++) {
                float p = expf(s[i][j] - mrow);
                ts[i] += p;
                Ps[(ty*4+i)*65 + tx*4 + j] = p;
            }
        }
        #pragma unroll
        for (int o = 1; o < 16; o <<= 1)
            #pragma unroll
            for (int i = 0; i < 4; i++)
                ts[i] += __shfl_xor_sync(0xffffffffu, ts[i], o);
        if (tx == 0) {
            #pragma unroll
            for (int i = 0; i < 4; i++) {
                int r = ty*4 + i;
                rl[r] = rl[r]*rf[r] + ts[i];
            }
        }
        __syncthreads();

        #pragma unroll
        for (int i = 0; i < 4; i++) {
            float f = rf[ty*4 + i];
            #pragma unroll
            for (int j = 0; j < 4; j++) acc[i][j] *= f;
        }
        #pragma unroll 8
        for (int c = 0; c < 64; c++) {
            float pv[4], vv[4];
            #pragma unroll
            for (int i = 0; i < 4; i++) pv[i] = Ps[(ty*4+i)*65 + c];
            #pragma unroll
            for (int j = 0; j < 4; j++) vv[j] = Vs[c*65 + tx*4 + j];
            #pragma unroll
            for (int i = 0; i < 4; i++)
                #pragma unroll
                for (int j = 0; j < 4; j++)
                    acc[i][j] += pv[i]*vv[j];
        }
        __syncthreads();
    }

    #pragma unroll
    for (int i = 0; i < 4; i++) {
        float inv = 1.0f / rl[ty*4 + i];
        #pragma unroll
        for (int j = 0; j < 4; j++)
            g_ctx[((size_t)b*LL + l0 + ty*4 + i)*HIDC + h*EE + tx*4 + j] =
                0.5f * acc[i][j] * inv;
    }
}

// ---------------- time-delay aggregation: ctx += 0.5 * sum_k w_k * V[(l+d_k)%L] ------
__global__ __launch_bounds__(256)
void delay_agg()
{
    __shared__ float ws[TOPK]; __shared__ int ds[TOPK];
    int l0 = blockIdx.x * 8, b = blockIdx.y, tid = threadIdx.x;
    if (tid < TOPK) { ws[tid] = g_wk[b*TOPK + tid]; ds[tid] = g_dk[b*TOPK + tid]; }
    __syncthreads();
    int c2 = tid;  // float2 index: 256 threads cover 512 floats
    const float2* Vb = (const float2*)(g_V + (size_t)b*LL*HIDC);
    float2 acc[8];
    #pragma unroll
    for (int i = 0; i < 8; i++) acc[i] = make_float2(0.f, 0.f);
    for (int k = 0; k < TOPK; k++) {
        float w = ws[k]; int d = ds[k];
        #pragma unroll
        for (int i = 0; i < 8; i++) {
            int pos = (l0 + i + d) & (LL - 1);
            float2 v = Vb[(size_t)pos*(HIDC/2) + c2];
            acc[i].x += w*v.x; acc[i].y += w*v.y;
        }
    }
    #pragma unroll
    for (int i = 0; i < 8; i++) {
        size_t off = ((size_t)b*LL + l0 + i)*(HIDC/2) + c2;
        float2* C = (float2*)g_ctx;
        float2 cur = C[off];
        cur.x += 0.5f*acc[i].x; cur.y += 0.5f*acc[i].y;
        C[off] = cur;
    }
}

// ---------------- layernorm ----------------
__global__ __launch_bounds__(128)
void ln_kernel(const float* __restrict__ hb, const float* __restrict__ w,
               const float* __restrict__ bp, float* __restrict__ out)
{
    int row = blockIdx.x, tid = threadIdx.x;
    const float* hr = hb + (size_t)row*HIDC;
    float4 xv = *(const float4*)&hr[tid*4];
    float s  = xv.x + xv.y + xv.z + xv.w;
    float ss = xv.x*xv.x + xv.y*xv.y + xv.z*xv.z + xv.w*xv.w;
    #pragma unroll
    for (int o = 16; o; o >>= 1) {
        s  += __shfl_xor_sync(0xffffffffu, s,  o);
        ss += __shfl_xor_sync(0xffffffffu, ss, o);
    }
    __shared__ float s1[4], s2s[4];
    int wp = tid >> 5;
    if ((tid & 31) == 0) { s1[wp] = s; s2s[wp] = ss; }
    __syncthreads();
    float st  = s1[0] + s1[1] + s1[2] + s1[3];
    float sst = s2s[0] + s2s[1] + s2s[2] + s2s[3];
    float mean = st * (1.0f / HIDC);
    float var  = fmaxf(sst * (1.0f / HIDC) - mean*mean, 0.0f);
    float inv  = rsqrtf(var + 1e-12f);
    int c = tid * 4;
    float4 o4;
    o4.x = w[c+0]*((xv.x - mean)*inv) + bp[c+0];
    o4.y = w[c+1]*((xv.y - mean)*inv) + bp[c+1];
    o4.z = w[c+2]*((xv.z - mean)*inv) + bp[c+2];
    o4.w = w[c+3]*((xv.w - mean)*inv) + bp[c+3];
    *(float4*)&out[(size_t)row*HIDC + c] = o4;
}

// ---------------- launch ----------------
extern "C" void kernel_launch(void* const* d_in, const int* in_sizes, int n_in,
                              void* d_out, int out_size)
{
    const float* x    = (const float*)d_in[0];
    const float* mask = (const float*)d_in[1];
    const float* Wq = (const float*)d_in[2];
    const float* bq = (const float*)d_in[3];
    const float* Wk = (const float*)d_in[4];
    const float* bk = (const float*)d_in[5];
    const float* Wv = (const float*)d_in[6];
    const float* bv = (const float*)d_in[7];
    const float* Wd = (const float*)d_in[8];
    const float* bd = (const float*)d_in[9];
    const float* lw = (const float*)d_in[10];
    const float* lb = (const float*)d_in[11];
    float* out = (float*)d_out;

    float *pQ,*pK,*pV,*pctx,*ph;
    cudaGetSymbolAddress((void**)&pQ,  g_Q);
    cudaGetSymbolAddress((void**)&pK,  g_K);
    cudaGetSymbolAddress((void**)&pV,  g_V);
    cudaGetSymbolAddress((void**)&pctx,g_ctx);
    cudaGetSymbolAddress((void**)&ph,  g_hb);

    const int M = BB * LL;   // 16384

    init_h<<<1, LL>>>();
    init_T<<<LL, LL>>>();

    // fused QKV via tf32 tensor cores: z selects weight set
    qkv_mma<<<dim3(M/128, HIDC/64, 3), 256>>>(x, Wq, bq, pQ, Wk, bk, pK, Wv, bv, pV);

    // Gram matrices + diagonal sums -> R -> topk weights
    gram_mma<<<dim3(LL/128, LL/64, BB), 256>>>();
    diag_sum<<<dim3(LL, BB), 128>>>();
    mc_topk<<<BB, 256>>>();

    // band filter via circulant GEMM (NN) for qs,ks,vs
    circ_mma<<<dim3(LL/128, HIDC/64, 3*BB), 256>>>();

    cudaFuncSetAttribute(attn_kernel, cudaFuncAttributeMaxDynamicSharedMemorySize,
                         4*64*65*sizeof(float));
    attn_kernel<<<dim3(LL/64, 1, BB*NHH), 256, 4*64*65*sizeof(float)>>>(mask);

    delay_agg<<<dim3(LL/8, BB), 256>>>();

    // output projection + residual via tf32 tensor cores
    outproj_mma<<<dim3(M/128, HIDC/64, 1), 256>>>(pctx, Wd, bd, x, ph);

    ln_kernel<<<M, 128>>>(ph, lw, lb, out);
}